// round 1
// baseline (speedup 1.0000x reference)
#include <cuda_runtime.h>
#include <math.h>

#define RING 256
#define DD   128
#define SD   42
#define G3   126     // 3*SD
#define BB   512
#define TT   512
#define NCLS 1000
#define INPD 64

// Scratch (static __device__ arrays: allowed; no runtime allocation)
__device__ float g_ring[(size_t)BB * RING * DD];      // 64 MB, fits L2
__device__ float g_gx[(size_t)BB * TT * G3];          // 132 MB precomputed gate inputs
__device__ float g_wct[INPD * 128];                   // fused (w_ih@w_proj) transposed, padded to 128 cols
__device__ float g_cc[128];                           // fused bias b_ih + w_ih@b_proj

// ---------------------------------------------------------------------------
// Kernel 0: fuse w_ih@w_proj -> Wct[i][j] (i-major, j padded to 128), cc[j]
// ---------------------------------------------------------------------------
__global__ void prep_kernel(const float* __restrict__ w_ih, const float* __restrict__ w_proj,
                            const float* __restrict__ b_ih, const float* __restrict__ b_proj) {
    int tid = blockIdx.x * blockDim.x + threadIdx.x;
    int nt  = gridDim.x * blockDim.x;
    for (int idx = tid; idx < INPD * 128; idx += nt) {
        int i = idx >> 7, j = idx & 127;
        float acc = 0.f;
        if (j < G3) {
            for (int k = 0; k < SD; k++)
                acc = fmaf(w_ih[j * SD + k], w_proj[k * INPD + i], acc);
        }
        g_wct[idx] = acc;
    }
    for (int j = tid; j < 128; j += nt) {
        float acc = 0.f;
        if (j < G3) {
            acc = b_ih[j];
            for (int k = 0; k < SD; k++) acc = fmaf(w_ih[j * SD + k], b_proj[k], acc);
        }
        g_cc[j] = acc;
    }
}

// ---------------------------------------------------------------------------
// Kernel 1: zero the ring state
// ---------------------------------------------------------------------------
__global__ void zero_ring_kernel() {
    size_t i = (size_t)blockIdx.x * blockDim.x + threadIdx.x;
    ((float4*)g_ring)[i] = make_float4(0.f, 0.f, 0.f, 0.f);
}

// ---------------------------------------------------------------------------
// Kernel 2: gx[row][j] = x[row] @ Wct + cc   for all rows = B*T  (parallel GEMM)
//   block: 256 threads, 32 rows; thread = (row r, 16-wide j group)
// ---------------------------------------------------------------------------
__global__ __launch_bounds__(256) void gx_kernel(const float* __restrict__ x) {
    __shared__ float xs[32 * INPD];
    __shared__ __align__(16) float wcs[INPD * 128];
    __shared__ float ccs[128];
    int tid = threadIdx.x;
    size_t row0 = (size_t)blockIdx.x * 32;

    for (int idx = tid; idx < 32 * INPD; idx += 256) xs[idx] = x[row0 * INPD + idx];
    for (int idx = tid; idx < INPD * 128; idx += 256) wcs[idx] = g_wct[idx];
    if (tid < 128) ccs[tid] = g_cc[tid];
    __syncthreads();

    int r  = tid >> 3;          // 0..31  row within tile
    int jg = (tid & 7) << 4;    // 0,16,...,112

    float acc[16];
#pragma unroll
    for (int q = 0; q < 16; q++) acc[q] = ccs[jg + q];

#pragma unroll 8
    for (int i = 0; i < INPD; i++) {
        float xv = xs[r * INPD + i];
        const float4* wr = (const float4*)(&wcs[i * 128 + jg]);
#pragma unroll
        for (int q = 0; q < 4; q++) {
            float4 w4 = wr[q];
            acc[q * 4 + 0] = fmaf(xv, w4.x, acc[q * 4 + 0]);
            acc[q * 4 + 1] = fmaf(xv, w4.y, acc[q * 4 + 1]);
            acc[q * 4 + 2] = fmaf(xv, w4.z, acc[q * 4 + 2]);
            acc[q * 4 + 3] = fmaf(xv, w4.w, acc[q * 4 + 3]);
        }
    }
    float* outp = &g_gx[(row0 + r) * (size_t)G3 + jg];
#pragma unroll
    for (int q = 0; q < 16; q++)
        if (jg + q < G3) outp[q] = acc[q];
}

// ---------------------------------------------------------------------------
// Sequential kernel helpers
// ---------------------------------------------------------------------------
__device__ __forceinline__ float sigm(float x) { return 1.0f / (1.0f + __expf(-x)); }

__device__ __forceinline__ void ringkern(float ptr, int* pos, float* wn) {
    float base = floorf(ptr);
    float frac = ptr - base;
    int ib = (int)base;
    float e[5];
    float s = 0.f;
#pragma unroll
    for (int k = 0; k < 5; k++) {
        pos[k] = (ib + k - 2 + RING) & (RING - 1);
        float dd = (float)(k - 2) - frac;
        e[k] = __expf(dd * dd * (-0.125f));
        s += e[k];
    }
    float inv = 1.0f / s;
#pragma unroll
    for (int k = 0; k < 5; k++) wn[k] = e[k] * inv;
}

// ---------------------------------------------------------------------------
// Kernel 3: sequential recurrence. One CTA per batch element, 128 threads.
//   thread d owns: ring column d, u_d, r_d, w_jump[d], w_gate[d]
//   ring in global (__ldcg/__stcg -> L2 only, keeps L1 for weights/gx)
// ---------------------------------------------------------------------------
__global__ __launch_bounds__(128, 4) void seq_kernel(
    const float* __restrict__ w_hh, const float* __restrict__ b_hh,
    const float* __restrict__ w_bridge, const float* __restrict__ b_bridge,
    const float* __restrict__ w_jump, const float* __restrict__ b_jump,
    const float* __restrict__ w_gate, const float* __restrict__ b_gate,
    const float* __restrict__ w_cls, const float* __restrict__ b_cls,
    const float* __restrict__ theta, float* __restrict__ out)
{
    __shared__ float whh_s[SD * 128];   // k-major: whh_s[k*128+j] = w_hh[j][k]
    __shared__ float wbr_s[SD * 128];   // k-major: wbr_s[k*128+d] = w_bridge[d][k]
    __shared__ float gx_s[128];
    __shared__ float gh_s[128];
    __shared__ float h_s[SD];
    __shared__ float red_s[8];

    const int tid = threadIdx.x;
    const int b   = blockIdx.x;

    for (int idx = tid; idx < G3 * SD; idx += 128) {
        int j = idx / SD, k = idx - j * SD;
        whh_s[k * 128 + j] = w_hh[idx];
    }
    for (int idx = tid; idx < DD * SD; idx += 128) {
        int d = idx / SD, k = idx - d * SD;
        wbr_s[k * 128 + d] = w_bridge[idx];
    }
    if (tid < SD) h_s[tid] = 0.f;

    float bhh = (tid < G3) ? b_hh[tid] : 0.f;
    float bbr = b_bridge[tid];
    float wj  = w_jump[tid];
    float wg  = w_gate[tid];
    float bj  = b_jump[0];
    float bg  = b_gate[0];

    float ptr = fmodf(theta[0], 256.f);
    if (ptr < 0.f) ptr += 256.f;

    float* ring     = g_ring + (size_t)b * RING * DD;
    const float* gx = g_gx   + (size_t)b * TT * G3;
    float gxv = (tid < G3) ? gx[tid] : 0.f;   // prefetch t=0
    __syncthreads();

    for (int t = 0; t < TT; t++) {
        // --- soft-kernel read weights at current ptr; issue ring loads early ---
        int pos[5]; float wn[5];
        ringkern(ptr, pos, wn);
        float rv0 = __ldcg(ring + pos[0] * DD + tid);
        float rv1 = __ldcg(ring + pos[1] * DD + tid);
        float rv2 = __ldcg(ring + pos[2] * DD + tid);
        float rv3 = __ldcg(ring + pos[3] * DD + tid);
        float rv4 = __ldcg(ring + pos[4] * DD + tid);

        // --- gh = h @ w_hh.T + b_hh  (126 rows), stage gx ---
        if (tid < G3) {
            float gh = bhh;
#pragma unroll
            for (int k = 0; k < SD; k++) gh = fmaf(whh_s[k * 128 + tid], h_s[k], gh);
            gh_s[tid] = gh;
            gx_s[tid] = gxv;
        }
        __syncthreads();   // B1: gh_s/gx_s ready, h_s(t-1) consumed

        // --- GRU gate math (threads 0..41) updates h in place ---
        if (tid < SD) {
            float rg = sigm(gx_s[tid] + gh_s[tid]);
            float zg = sigm(gx_s[SD + tid] + gh_s[SD + tid]);
            float ng = tanhf(gx_s[2 * SD + tid] + rg * gh_s[2 * SD + tid]);
            float hp = h_s[tid];
            h_s[tid] = (1.f - zg) * ng + zg * hp;
        }

        // --- finish ring read, jump/gate dot partials (all 128 threads) ---
        float racc = fmaf(wn[0], rv0,
                     fmaf(wn[1], rv1,
                     fmaf(wn[2], rv2,
                     fmaf(wn[3], rv3, wn[4] * rv4))));
        float jp = wj * racc;
        float gp = wg * racc;
#pragma unroll
        for (int o = 16; o > 0; o >>= 1) {
            jp += __shfl_xor_sync(0xffffffffu, jp, o);
            gp += __shfl_xor_sync(0xffffffffu, gp, o);
        }
        if ((tid & 31) == 0) {
            int w = tid >> 5;
            red_s[w]     = jp;
            red_s[4 + w] = gp;
        }
        __syncthreads();   // B2: h new + reduction partials ready

        // --- u = tanh(h_new @ w_bridge.T + b) ---
        float u = bbr;
#pragma unroll
        for (int k = 0; k < SD; k++) u = fmaf(wbr_s[k * 128 + tid], h_s[k], u);
        u = tanhf(u);

        // --- pointer update (computed redundantly by all threads, fixed order) ---
        float jd = ((red_s[0] + red_s[1]) + (red_s[2] + red_s[3])) + bj;
        float gd = ((red_s[4] + red_s[5]) + (red_s[6] + red_s[7])) + bg;
        float jump = sigm(jd) * 256.f;
        float gate = sigm(gd);
        float delta = fmodf((jump - ptr) + 128.f, 256.f);
        if (delta < 0.f) delta += 256.f;
        delta -= 128.f;
        float stepv = __fmul_rn(gate, delta);
        ptr = fmodf(__fadd_rn(ptr, stepv), 256.f);
        if (ptr < 0.f) ptr += 256.f;

        // --- soft-kernel write at new ptr (column d owned by this thread) ---
        int pos2[5]; float wn2[5];
        ringkern(ptr, pos2, wn2);

        // prefetch next gx while write latency flies
        if (tid < G3) gxv = gx[(t + 1 < TT ? t + 1 : TT - 1) * G3 + tid];

#pragma unroll
        for (int k = 0; k < 5; k++) {
            float* a = ring + pos2[k] * DD + tid;
            __stcg(a, fmaf(wn2[k], u, __ldcg(a)));
        }
        // next step's reads of this column are same-thread, program-ordered: no sync
    }

    // --- final read at final ptr ---
    int pos[5]; float wn[5];
    ringkern(ptr, pos, wn);
    float rf = 0.f;
#pragma unroll
    for (int k = 0; k < 5; k++)
        rf = fmaf(wn[k], __ldcg(ring + pos[k] * DD + tid), rf);
    gh_s[tid] = rf;
    __syncthreads();

    // --- fused classifier: logits[b][n] = r @ w_cls[n] + b_cls[n] ---
    for (int n = tid; n < NCLS; n += 128) {
        float acc = b_cls[n];
        const float4* wr = (const float4*)(w_cls + (size_t)n * DD);
#pragma unroll 8
        for (int q = 0; q < 32; q++) {
            float4 w4 = wr[q];
            acc = fmaf(gh_s[q * 4 + 0], w4.x, acc);
            acc = fmaf(gh_s[q * 4 + 1], w4.y, acc);
            acc = fmaf(gh_s[q * 4 + 2], w4.z, acc);
            acc = fmaf(gh_s[q * 4 + 3], w4.w, acc);
        }
        out[(size_t)b * NCLS + n] = acc;
    }
}

// ---------------------------------------------------------------------------
extern "C" void kernel_launch(void* const* d_in, const int* in_sizes, int n_in,
                              void* d_out, int out_size) {
    const float* x        = (const float*)d_in[0];
    const float* theta    = (const float*)d_in[1];
    const float* w_proj   = (const float*)d_in[2];
    const float* b_proj   = (const float*)d_in[3];
    const float* w_ih     = (const float*)d_in[4];
    const float* w_hh     = (const float*)d_in[5];
    const float* b_ih     = (const float*)d_in[6];
    const float* b_hh     = (const float*)d_in[7];
    const float* w_bridge = (const float*)d_in[8];
    const float* b_bridge = (const float*)d_in[9];
    const float* w_jump   = (const float*)d_in[10];
    const float* b_jump   = (const float*)d_in[11];
    const float* w_gate   = (const float*)d_in[12];
    const float* b_gate   = (const float*)d_in[13];
    const float* w_cls    = (const float*)d_in[14];
    const float* b_cls    = (const float*)d_in[15];
    float* out = (float*)d_out;

    prep_kernel<<<16, 256>>>(w_ih, w_proj, b_ih, b_proj);
    zero_ring_kernel<<<(BB * RING * DD / 4) / 1024, 1024>>>();
    gx_kernel<<<(BB * TT) / 32, 256>>>(x);
    seq_kernel<<<BB, 128>>>(w_hh, b_hh, w_bridge, b_bridge,
                            w_jump, b_jump, w_gate, b_gate,
                            w_cls, b_cls, theta, out);
}

// round 4
// speedup vs baseline: 1.2117x; 1.2117x over previous
#include <cuda_runtime.h>
#include <math.h>

#define RING 256
#define DD   128
#define SD   42
#define G3   126
#define BB   512
#define TT   512
#define NCLS 1000
#define INPD 64

// static device scratch (no runtime allocation)
__device__ float g_gx[(size_t)BB * TT * G3];     // 132 MB: precomputed gate inputs
__device__ float g_u [(size_t)BB * TT * DD];     // 134 MB: per-step write vectors
__device__ float g_wct[INPD * 128];              // fused (w_ih@w_proj)^T, j padded to 128
__device__ float g_cc[128];                      // fused bias

// ---------------- packed f32x2 helpers ----------------
__device__ __forceinline__ unsigned long long pack2(float a, float b) {
    unsigned long long r; asm("mov.b64 %0,{%1,%2};" : "=l"(r) : "f"(a), "f"(b)); return r;
}
__device__ __forceinline__ void fma2(unsigned long long& acc, unsigned long long a, unsigned long long b) {
    asm("fma.rn.f32x2 %0,%1,%2,%0;" : "+l"(acc) : "l"(a), "l"(b));
}
__device__ __forceinline__ float unpack_sum(unsigned long long a) {
    float lo, hi; asm("mov.b64 {%0,%1},%2;" : "=f"(lo), "=f"(hi) : "l"(a)); return lo + hi;
}

__device__ __forceinline__ float sigm(float x) {
    return __fdividef(1.0f, 1.0f + __expf(-x));
}
__device__ __forceinline__ float tanh_fast(float x) {
    float s = __fdividef(1.0f, 1.0f + __expf(-2.0f * x));
    return fmaf(2.0f, s, -1.0f);
}

// Gaussian soft window: wn[k] ∝ exp(-(k-2-frac)^2/8), softmax-normalized.
// exp(-(o-f)^2/8) ∝ C[o]*y^o with y=e^{f/4}, C[o]=e^{-o^2/8}  (common factor cancels)
#define CK1 0.8824969025845954f   /* e^{-1/8} */
#define CK2 0.6065306597126334f   /* e^{-1/2} */
__device__ __forceinline__ void ringkern(float p, int* pos, float* wn) {
    float base = floorf(p);
    float frac = p - base;
    int ib = (int)base;
#pragma unroll
    for (int k = 0; k < 5; k++) pos[k] = (ib + k - 2) & (RING - 1);
    float y  = __expf(frac * 0.25f);
    float yi = __fdividef(1.0f, y);
    float e0 = CK2 * yi * yi, e1 = CK1 * yi, e2 = 1.0f, e3 = CK1 * y, e4 = CK2 * y * y;
    float inv = __fdividef(1.0f, e0 + e1 + e2 + e3 + e4);
    wn[0] = e0 * inv; wn[1] = e1 * inv; wn[2] = e2 * inv; wn[3] = e3 * inv; wn[4] = e4 * inv;
}

// 42-dim dot: packed weights (21 x f32x2) vs h_s (smem), 2 indep chains
__device__ __forceinline__ float dot42(const unsigned long long* w, const float* h_s) {
    const ulonglong2* hp = (const ulonglong2*)h_s;
    unsigned long long a0 = 0ull, a1 = 0ull;
#pragma unroll
    for (int q = 0; q < 10; q++) {
        ulonglong2 hh = hp[q];
        fma2(a0, w[2 * q], hh.x);
        fma2(a1, w[2 * q + 1], hh.y);
    }
    fma2(a0, w[20], ((const unsigned long long*)h_s)[20]);
    return unpack_sum(a0) + unpack_sum(a1);
}

// ---------------------------------------------------------------------------
// Kernel 0: fuse w_ih@w_proj -> g_wct[i*128+j], g_cc[j]
// ---------------------------------------------------------------------------
__global__ void prep_kernel(const float* __restrict__ w_ih, const float* __restrict__ w_proj,
                            const float* __restrict__ b_ih, const float* __restrict__ b_proj) {
    int tid = blockIdx.x * blockDim.x + threadIdx.x;
    int nt  = gridDim.x * blockDim.x;
    for (int idx = tid; idx < INPD * 128; idx += nt) {
        int i = idx >> 7, j = idx & 127;
        float acc = 0.f;
        if (j < G3)
            for (int k = 0; k < SD; k++)
                acc = fmaf(w_ih[j * SD + k], w_proj[k * INPD + i], acc);
        g_wct[idx] = acc;
    }
    for (int j = tid; j < 128; j += nt) {
        float acc = 0.f;
        if (j < G3) {
            acc = b_ih[j];
            for (int k = 0; k < SD; k++) acc = fmaf(w_ih[j * SD + k], b_proj[k], acc);
        }
        g_cc[j] = acc;
    }
}

// ---------------------------------------------------------------------------
// Kernel 1: gx = x @ Wct + cc  — 32 rows/block (smem fits 48KB), f32x2 math
// ---------------------------------------------------------------------------
__global__ __launch_bounds__(256, 2) void gx_kernel(const float* __restrict__ x) {
    __shared__ float xs[32 * INPD];                      // 8 KB
    __shared__ __align__(16) float wcs[INPD * 128];      // 32 KB
    __shared__ float ccs[128];                           // 0.5 KB   total 40.7 KB
    int tid = threadIdx.x;
    size_t row0 = (size_t)blockIdx.x * 32;

    for (int i = tid; i < 32 * INPD; i += 256) xs[i] = x[row0 * INPD + i];
    for (int i = tid; i < INPD * 128; i += 256) wcs[i] = g_wct[i];
    if (tid < 128) ccs[tid] = g_cc[tid];
    __syncthreads();

    int r  = tid >> 3;           // 0..31
    int jg = (tid & 7) << 4;     // 0..112

    unsigned long long acc[8];
#pragma unroll
    for (int q = 0; q < 8; q++)
        acc[q] = pack2(ccs[jg + 2 * q], ccs[jg + 2 * q + 1]);

#pragma unroll 8
    for (int i = 0; i < INPD; i++) {
        float xv = xs[r * INPD + i];
        unsigned long long xp = pack2(xv, xv);
        const ulonglong2* wr = (const ulonglong2*)&wcs[i * 128 + jg];
#pragma unroll
        for (int q2 = 0; q2 < 4; q2++) {
            ulonglong2 w2 = wr[q2];
            fma2(acc[2 * q2],     xp, w2.x);
            fma2(acc[2 * q2 + 1], xp, w2.y);
        }
    }
    float* o0 = &g_gx[(row0 + r) * (size_t)G3];
#pragma unroll
    for (int q = 0; q < 8; q++) {
        float lo, hi;
        asm("mov.b64 {%0,%1},%2;" : "=f"(lo), "=f"(hi) : "l"(acc[q]));
        int j = jg + 2 * q;
        if (j < G3)     o0[j]     = lo;
        if (j + 1 < G3) o0[j + 1] = hi;
    }
}

// ---------------------------------------------------------------------------
// Kernel 2: sequential recurrence. 1 CTA / batch, 128 threads.
//   warps 0-2: GRU/bridge compute; warp 3: scalar pointer engine on smem
//   J/G ring summaries (exact linear rewrite of jump/gate dot products).
//   Full ring never materialized; u streamed to global, final soft-read
//   reconstructed from the pointer history after the loop.
// ---------------------------------------------------------------------------
__global__ __launch_bounds__(128, 4) void seq_kernel(
    const float* __restrict__ w_hh, const float* __restrict__ b_hh,
    const float* __restrict__ w_bridge, const float* __restrict__ b_bridge,
    const float* __restrict__ w_jump, const float* __restrict__ b_jump,
    const float* __restrict__ w_gate, const float* __restrict__ b_gate,
    const float* __restrict__ w_cls, const float* __restrict__ b_cls,
    const float* __restrict__ theta, float* __restrict__ out)
{
    __shared__ __align__(16) float h_s[44];
    __shared__ float gh_s[128];
    __shared__ float red_s[8];
    __shared__ float J_s[RING];
    __shared__ float G_s[RING];
    __shared__ float hist_s[TT];

    const int tid  = threadIdx.x;
    const int lane = tid & 31;
    const int wid  = tid >> 5;
    const int b    = blockIdx.x;

    for (int i = tid; i < RING; i += 128) { J_s[i] = 0.f; G_s[i] = 0.f; }
    if (tid < 44) h_s[tid] = 0.f;

    // per-thread weight columns, packed f32x2
    unsigned long long whh_r[21], wbr_r[21];
    if (tid < G3) {
#pragma unroll
        for (int q = 0; q < 21; q++)
            whh_r[q] = pack2(w_hh[tid * SD + 2 * q], w_hh[tid * SD + 2 * q + 1]);
    } else {
#pragma unroll
        for (int q = 0; q < 21; q++) whh_r[q] = 0ull;
    }
#pragma unroll
    for (int q = 0; q < 21; q++)
        wbr_r[q] = pack2(w_bridge[tid * SD + 2 * q], w_bridge[tid * SD + 2 * q + 1]);

    const float bhh = (tid < G3) ? b_hh[tid] : 0.f;
    const float bbr = b_bridge[tid];
    const float wj  = w_jump[tid];
    const float wg  = w_gate[tid];
    const float bj  = b_jump[0];
    const float bg  = b_gate[0];

    float ptr = fmodf(theta[0], 256.f);
    if (ptr < 0.f) ptr += 256.f;

    const float* gx = g_gx + (size_t)b * TT * G3;
    float*       up = g_u  + (size_t)b * TT * DD;

    float gx0 = 0.f, gx1 = 0.f, gx2 = 0.f;
    if (tid < SD) {
        gx0 = __ldcs(gx + tid);
        gx1 = __ldcs(gx + SD + tid);
        gx2 = __ldcs(gx + 2 * SD + tid);
    }
    __syncthreads();

    for (int t = 0; t < TT; t++) {
        // ---- gh = h @ w_hh^T + b_hh ----
        if (tid < G3) gh_s[tid] = dot42(whh_r, h_s) + bhh;
        __syncthreads();                               // B1

        // ---- GRU (threads<42)  ||  warp3: ptr read+advance ----
        if (tid < SD) {
            float rg = sigm(gx0 + gh_s[tid]);
            float zg = sigm(gx1 + gh_s[SD + tid]);
            float ng = tanh_fast(gx2 + rg * gh_s[2 * SD + tid]);
            h_s[tid] = (1.f - zg) * ng + zg * h_s[tid];
        } else if (wid == 3) {
            int pos[5]; float wn[5];
            ringkern(ptr, pos, wn);
            float jd = bj, gd = bg;
#pragma unroll
            for (int k = 0; k < 5; k++) {
                jd = fmaf(wn[k], J_s[pos[k]], jd);
                gd = fmaf(wn[k], G_s[pos[k]], gd);
            }
            float jump = sigm(jd) * 256.f;
            float gate = sigm(gd);
            float dlt = fmodf(jump - ptr + 128.f, 256.f);
            if (dlt < 0.f) dlt += 256.f;
            dlt -= 128.f;
            ptr = fmodf(ptr + gate * dlt, 256.f);
            if (ptr < 0.f) ptr += 256.f;
        }
        __syncthreads();                               // B2

        // ---- u = tanh(h @ w_bridge^T + b) ; reduce jump/gate dots ----
        float u = tanh_fast(dot42(wbr_r, h_s) + bbr);
        __stcs(up + (size_t)t * DD + tid, u);
        float jp = wj * u, gp = wg * u;
#pragma unroll
        for (int o = 16; o > 0; o >>= 1) {
            jp += __shfl_xor_sync(0xffffffffu, jp, o);
            gp += __shfl_xor_sync(0xffffffffu, gp, o);
        }
        if (lane == 0) { red_s[wid] = jp; red_s[4 + wid] = gp; }
        // prefetch next gx during the store/shuffle shadow
        if (tid < SD) {
            int tn = (t + 1 < TT) ? t + 1 : TT - 1;
            gx0 = __ldcs(gx + (size_t)tn * G3 + tid);
            gx1 = __ldcs(gx + (size_t)tn * G3 + SD + tid);
            gx2 = __ldcs(gx + (size_t)tn * G3 + 2 * SD + tid);
        }
        __syncthreads();                               // B3

        // ---- warp3: apply write to J/G summaries at new ptr ----
        if (wid == 3) {
            float ju = (red_s[0] + red_s[1]) + (red_s[2] + red_s[3]);
            float gu = (red_s[4] + red_s[5]) + (red_s[6] + red_s[7]);
            int pos2[5]; float wn2[5];
            ringkern(ptr, pos2, wn2);
#pragma unroll
            for (int k = 0; k < 5; k++) {
                J_s[pos2[k]] += wn2[k] * ju;
                G_s[pos2[k]] += wn2[k] * gu;
            }
            hist_s[t] = ptr;
        }
    }
    __syncthreads();

    // ---- reconstruct final soft read from u history ----
    float pF = hist_s[TT - 1];
    int posf[5]; float wnf[5];
    ringkern(pF, posf, wnf);
    int ib_f = (int)floorf(pF);
    float rf = 0.f;
    for (int t = 0; t < TT; t++) {
        float pt = hist_s[t];
        int ib_t = (int)floorf(pt);
        int dw = ((ib_t - ib_f + 128) & 255) - 128;
        if (dw > -5 && dw < 5) {
            int pd[5]; float wn2[5];
            ringkern(pt, pd, wn2);
            float coef = 0.f;
#pragma unroll
            for (int k = 0; k < 5; k++) {
                int m = k + dw;
                if (m >= 0 && m < 5) coef = fmaf(wnf[m], wn2[k], coef);
            }
            rf = fmaf(coef, up[(size_t)t * DD + tid], rf);
        }
    }
    gh_s[tid] = rf;
    __syncthreads();

    // ---- fused classifier ----
    for (int n = tid; n < NCLS; n += 128) {
        float acc = b_cls[n];
        const float4* wr = (const float4*)(w_cls + (size_t)n * DD);
#pragma unroll 8
        for (int q = 0; q < 32; q++) {
            float4 w4 = wr[q];
            acc = fmaf(gh_s[q * 4 + 0], w4.x, acc);
            acc = fmaf(gh_s[q * 4 + 1], w4.y, acc);
            acc = fmaf(gh_s[q * 4 + 2], w4.z, acc);
            acc = fmaf(gh_s[q * 4 + 3], w4.w, acc);
        }
        out[(size_t)b * NCLS + n] = acc;
    }
}

// ---------------------------------------------------------------------------
extern "C" void kernel_launch(void* const* d_in, const int* in_sizes, int n_in,
                              void* d_out, int out_size) {
    const float* x        = (const float*)d_in[0];
    const float* theta    = (const float*)d_in[1];
    const float* w_proj   = (const float*)d_in[2];
    const float* b_proj   = (const float*)d_in[3];
    const float* w_ih     = (const float*)d_in[4];
    const float* w_hh     = (const float*)d_in[5];
    const float* b_ih     = (const float*)d_in[6];
    const float* b_hh     = (const float*)d_in[7];
    const float* w_bridge = (const float*)d_in[8];
    const float* b_bridge = (const float*)d_in[9];
    const float* w_jump   = (const float*)d_in[10];
    const float* b_jump   = (const float*)d_in[11];
    const float* w_gate   = (const float*)d_in[12];
    const float* b_gate   = (const float*)d_in[13];
    const float* w_cls    = (const float*)d_in[14];
    const float* b_cls    = (const float*)d_in[15];
    float* out = (float*)d_out;

    prep_kernel<<<16, 256>>>(w_ih, w_proj, b_ih, b_proj);
    gx_kernel<<<(BB * TT) / 32, 256>>>(x);
    seq_kernel<<<BB, 128>>>(w_hh, b_hh, w_bridge, b_bridge,
                            w_jump, b_jump, w_gate, b_gate,
                            w_cls, b_cls, theta, out);
}